// round 1
// baseline (speedup 1.0000x reference)
#include <cuda_runtime.h>
#include <cuda_bf16.h>
#include <mma.h>

using namespace nvcuda;

// Problem constants
#define N_ROWS 8192
#define K_IN   4096
#define M_OUT  4096
#define R_LORA 16
#define KP     4128   // 4096 (x/W) + 16 (T/B_lora) + 1 (ones/b) + 15 zero pad
#define SCALING 2.0f

// Scratch (device globals — no allocation at runtime)
__device__ __nv_bfloat16 g_x_hi[(size_t)N_ROWS * KP];
__device__ __nv_bfloat16 g_x_lo[(size_t)N_ROWS * KP];
__device__ __nv_bfloat16 g_w_hi[(size_t)M_OUT * KP];
__device__ __nv_bfloat16 g_w_lo[(size_t)M_OUT * KP];
__device__ float         g_T[(size_t)N_ROWS * R_LORA];   // SCALING * x @ A^T

// ---------------------------------------------------------------------------
// Kernel 1: T = SCALING * x @ A^T   (N x 16), fp32 exact.
// 256 threads, 32 rows per block, grid = 256 blocks.
// ---------------------------------------------------------------------------
__global__ void lora_T_kernel(const float* __restrict__ x,
                              const float* __restrict__ A) {
    __shared__ float sA[16][65];
    __shared__ float sX[32][65];
    const int tid = threadIdx.x;
    const int rowBase = blockIdx.x * 32;
    const int rowLoc = tid & 31;          // 0..31
    const int rGroup = tid >> 5;          // 0..7 -> 2 r values each

    float acc0 = 0.f, acc1 = 0.f;

    for (int k0 = 0; k0 < K_IN; k0 += 64) {
        // load A chunk [16][64]
        for (int i = tid; i < 16 * 64; i += 256) {
            int r = i >> 6, kk = i & 63;
            sA[r][kk] = A[r * K_IN + k0 + kk];
        }
        // load x chunk [32][64] (coalesced along k)
        for (int i = tid; i < 32 * 64; i += 256) {
            int rr = i >> 6, kk = i & 63;
            sX[rr][kk] = x[(size_t)(rowBase + rr) * K_IN + k0 + kk];
        }
        __syncthreads();
        #pragma unroll 16
        for (int kk = 0; kk < 64; kk++) {
            float xv = sX[rowLoc][kk];
            acc0 += xv * sA[rGroup * 2 + 0][kk];
            acc1 += xv * sA[rGroup * 2 + 1][kk];
        }
        __syncthreads();
    }
    const int row = rowBase + rowLoc;
    g_T[(size_t)row * R_LORA + rGroup * 2 + 0] = acc0 * SCALING;
    g_T[(size_t)row * R_LORA + rGroup * 2 + 1] = acc1 * SCALING;
}

// ---------------------------------------------------------------------------
// Kernel 2: pack augmented X into bf16 hi/lo.
// Column layout: [0,4096) = x ; [4096,4112) = T ; 4112 = 1.0 ; rest 0.
// grid = ((KP+255)/256, N_ROWS)
// ---------------------------------------------------------------------------
__global__ void pack_x_kernel(const float* __restrict__ x) {
    const int k = blockIdx.x * blockDim.x + threadIdx.x;
    const int n = blockIdx.y;
    if (k >= KP) return;
    float v;
    if (k < K_IN)               v = x[(size_t)n * K_IN + k];
    else if (k < K_IN + R_LORA) v = g_T[(size_t)n * R_LORA + (k - K_IN)];
    else if (k == K_IN + R_LORA) v = 1.0f;
    else                        v = 0.0f;
    __nv_bfloat16 h = __float2bfloat16(v);
    const size_t idx = (size_t)n * KP + k;
    g_x_hi[idx] = h;
    g_x_lo[idx] = __float2bfloat16(v - __bfloat162float(h));
}

// ---------------------------------------------------------------------------
// Kernel 3: pack augmented W into bf16 hi/lo.
// Row o: [0,4096)=W[o,:], [4096,4112)=lora_B[o,:], 4112=b[o], rest 0.
// ---------------------------------------------------------------------------
__global__ void pack_w_kernel(const float* __restrict__ W,
                              const float* __restrict__ b,
                              const float* __restrict__ loraB) {
    const int k = blockIdx.x * blockDim.x + threadIdx.x;
    const int o = blockIdx.y;
    if (k >= KP) return;
    float v;
    if (k < K_IN)               v = W[(size_t)o * K_IN + k];
    else if (k < K_IN + R_LORA) v = loraB[(size_t)o * R_LORA + (k - K_IN)];
    else if (k == K_IN + R_LORA) v = b[o];
    else                        v = 0.0f;
    __nv_bfloat16 h = __float2bfloat16(v);
    const size_t idx = (size_t)o * KP + k;
    g_w_hi[idx] = h;
    g_w_lo[idx] = __float2bfloat16(v - __bfloat162float(h));
}

// ---------------------------------------------------------------------------
// Kernel 4: C = Xaug_split @ Waug_split^T  (split-bf16, fp32 accum).
// Block tile 128x128, BK=32, 8 warps in 2(M) x 4(N), warp tile 64x32.
// 3 HMMA per C-tile per 16-k sub-step (hh, hl, lh).
// ---------------------------------------------------------------------------
#define BM 128
#define BN 128
#define BK 32
#define LDS 40   // BK + 8 skew (bf16 elems); 80B row pitch, 16B aligned

__global__ __launch_bounds__(256, 1) void gemm_kernel(float* __restrict__ out) {
    __shared__ __align__(16) __nv_bfloat16 sXh[BM][LDS];
    __shared__ __align__(16) __nv_bfloat16 sXl[BM][LDS];
    __shared__ __align__(16) __nv_bfloat16 sWh[BN][LDS];
    __shared__ __align__(16) __nv_bfloat16 sWl[BN][LDS];

    const int tid  = threadIdx.x;
    const int warp = tid >> 5;
    const int wm = warp >> 2;     // 0..1 : M offset wm*64
    const int wn = warp & 3;      // 0..3 : N offset wn*32
    const int blockM = blockIdx.y * BM;
    const int blockN = blockIdx.x * BN;

    wmma::fragment<wmma::accumulator, 16, 16, 16, float> c[4][2];
    #pragma unroll
    for (int i = 0; i < 4; i++)
        #pragma unroll
        for (int j = 0; j < 2; j++)
            wmma::fill_fragment(c[i][j], 0.0f);

    for (int k0 = 0; k0 < KP; k0 += BK) {
        // Stage tiles: each tile is 128 rows x 32 bf16 = 512 uint4.
        #pragma unroll
        for (int t = tid; t < 512; t += 256) {
            const int r  = t >> 2;
            const int c4 = t & 3;
            const size_t gx = (size_t)(blockM + r) * KP + k0 + c4 * 8;
            const size_t gw = (size_t)(blockN + r) * KP + k0 + c4 * 8;
            *(uint4*)&sXh[r][c4 * 8] = *(const uint4*)&g_x_hi[gx];
            *(uint4*)&sXl[r][c4 * 8] = *(const uint4*)&g_x_lo[gx];
            *(uint4*)&sWh[r][c4 * 8] = *(const uint4*)&g_w_hi[gw];
            *(uint4*)&sWl[r][c4 * 8] = *(const uint4*)&g_w_lo[gw];
        }
        __syncthreads();

        #pragma unroll
        for (int ks = 0; ks < 2; ks++) {
            wmma::fragment<wmma::matrix_a, 16, 16, 16, __nv_bfloat16, wmma::row_major> ah[4], al[4];
            wmma::fragment<wmma::matrix_b, 16, 16, 16, __nv_bfloat16, wmma::col_major> bh[2], bl[2];
            #pragma unroll
            for (int i = 0; i < 4; i++) {
                wmma::load_matrix_sync(ah[i], &sXh[wm * 64 + i * 16][ks * 16], LDS);
                wmma::load_matrix_sync(al[i], &sXl[wm * 64 + i * 16][ks * 16], LDS);
            }
            #pragma unroll
            for (int j = 0; j < 2; j++) {
                wmma::load_matrix_sync(bh[j], &sWh[wn * 32 + j * 16][ks * 16], LDS);
                wmma::load_matrix_sync(bl[j], &sWl[wn * 32 + j * 16][ks * 16], LDS);
            }
            #pragma unroll
            for (int i = 0; i < 4; i++)
                #pragma unroll
                for (int j = 0; j < 2; j++) {
                    wmma::mma_sync(c[i][j], ah[i], bh[j], c[i][j]);
                    wmma::mma_sync(c[i][j], ah[i], bl[j], c[i][j]);
                    wmma::mma_sync(c[i][j], al[i], bh[j], c[i][j]);
                }
        }
        __syncthreads();
    }

    #pragma unroll
    for (int i = 0; i < 4; i++)
        #pragma unroll
        for (int j = 0; j < 2; j++) {
            float* dst = &out[(size_t)(blockM + wm * 64 + i * 16) * M_OUT +
                              blockN + wn * 32 + j * 16];
            wmma::store_matrix_sync(dst, c[i][j], M_OUT, wmma::mem_row_major);
        }
}

// ---------------------------------------------------------------------------
// Launch
// ---------------------------------------------------------------------------
extern "C" void kernel_launch(void* const* d_in, const int* in_sizes, int n_in,
                              void* d_out, int out_size) {
    const float* x     = (const float*)d_in[0];   // [N, IN]
    const float* W     = (const float*)d_in[1];   // [OUT, IN]
    const float* b     = (const float*)d_in[2];   // [OUT]
    const float* loraA = (const float*)d_in[3];   // [R, IN]
    const float* loraB = (const float*)d_in[4];   // [OUT, R]
    float* out = (float*)d_out;                   // [N, OUT]

    // 1. LoRA intermediate T = SCALING * x @ A^T (fp32 exact)
    lora_T_kernel<<<N_ROWS / 32, 256>>>(x, loraA);

    // 2./3. pack augmented operands into split-bf16
    dim3 pg((KP + 255) / 256, N_ROWS);
    pack_x_kernel<<<pg, 256>>>(x);
    dim3 pw((KP + 255) / 256, M_OUT);
    pack_w_kernel<<<pw, 256>>>(W, b, loraB);

    // 4. fused GEMM (bias + LoRA folded into augmented K)
    dim3 gg(M_OUT / BN, N_ROWS / BM);
    gemm_kernel<<<gg, 256>>>(out);
}

// round 3
// speedup vs baseline: 4.8216x; 4.8216x over previous
#include <cuda_runtime.h>
#include <cuda_fp16.h>
#include <mma.h>
#include <cstdint>

using namespace nvcuda;

// ---------------------------------------------------------------------------
// Problem constants
// ---------------------------------------------------------------------------
#define N_ROWS 8192
#define K_IN   4096
#define M_OUT  4096
#define R_LORA 16
#define KP     4160          // 4096 + 16 (LoRA) + 1 (bias) + 47 zero pad = 65*64
#define NCHUNK 65            // KP / 64
#define SCALING 2.0f

// Scratch (device globals — no runtime allocation). ~103 MB total.
__device__ __half g_x[(size_t)N_ROWS * KP];
__device__ __half g_w[(size_t)M_OUT * KP];
__device__ float  g_T[(size_t)N_ROWS * R_LORA];

// ---------------------------------------------------------------------------
// Kernel 1: T = SCALING * x @ A^T   (N x 16), fp32 exact.
// ---------------------------------------------------------------------------
__global__ void lora_T_kernel(const float* __restrict__ x,
                              const float* __restrict__ A) {
    __shared__ float sA[16][65];
    __shared__ float sX[32][65];
    const int tid = threadIdx.x;
    const int rowBase = blockIdx.x * 32;
    const int rowLoc = tid & 31;
    const int rGroup = tid >> 5;

    float acc0 = 0.f, acc1 = 0.f;
    for (int k0 = 0; k0 < K_IN; k0 += 64) {
        for (int i = tid; i < 16 * 64; i += 256) {
            int r = i >> 6, kk = i & 63;
            sA[r][kk] = A[r * K_IN + k0 + kk];
        }
        for (int i = tid; i < 32 * 64; i += 256) {
            int rr = i >> 6, kk = i & 63;
            sX[rr][kk] = x[(size_t)(rowBase + rr) * K_IN + k0 + kk];
        }
        __syncthreads();
        #pragma unroll 16
        for (int kk = 0; kk < 64; kk++) {
            float xv = sX[rowLoc][kk];
            acc0 += xv * sA[rGroup * 2 + 0][kk];
            acc1 += xv * sA[rGroup * 2 + 1][kk];
        }
        __syncthreads();
    }
    const int row = rowBase + rowLoc;
    g_T[(size_t)row * R_LORA + rGroup * 2 + 0] = acc0 * SCALING;
    g_T[(size_t)row * R_LORA + rGroup * 2 + 1] = acc1 * SCALING;
}

// ---------------------------------------------------------------------------
// Kernels 2/3: pack augmented operands into fp16. One thread = 8 columns
// (two float4 reads, one 16B write).
// ---------------------------------------------------------------------------
#define C8_PER_ROW (KP / 8)   // 520

__global__ void pack_x_kernel(const float* __restrict__ x) {
    const size_t idx = (size_t)blockIdx.x * blockDim.x + threadIdx.x;
    const int row = (int)(idx / C8_PER_ROW);
    const int c8  = (int)(idx % C8_PER_ROW);
    if (row >= N_ROWS) return;
    __half h[8];
    if (c8 < K_IN / 8) {
        const float4 v0 = *(const float4*)&x[(size_t)row * K_IN + c8 * 8];
        const float4 v1 = *(const float4*)&x[(size_t)row * K_IN + c8 * 8 + 4];
        h[0] = __float2half_rn(v0.x); h[1] = __float2half_rn(v0.y);
        h[2] = __float2half_rn(v0.z); h[3] = __float2half_rn(v0.w);
        h[4] = __float2half_rn(v1.x); h[5] = __float2half_rn(v1.y);
        h[6] = __float2half_rn(v1.z); h[7] = __float2half_rn(v1.w);
    } else {
        #pragma unroll
        for (int j = 0; j < 8; j++) {
            const int k = c8 * 8 + j;
            float v;
            if (k < K_IN + R_LORA)       v = g_T[(size_t)row * R_LORA + (k - K_IN)];
            else if (k == K_IN + R_LORA) v = 1.0f;
            else                         v = 0.0f;
            h[j] = __float2half_rn(v);
        }
    }
    *(uint4*)&g_x[(size_t)row * KP + c8 * 8] = *(const uint4*)h;
}

__global__ void pack_w_kernel(const float* __restrict__ W,
                              const float* __restrict__ b,
                              const float* __restrict__ loraB) {
    const size_t idx = (size_t)blockIdx.x * blockDim.x + threadIdx.x;
    const int o  = (int)(idx / C8_PER_ROW);
    const int c8 = (int)(idx % C8_PER_ROW);
    if (o >= M_OUT) return;
    __half h[8];
    if (c8 < K_IN / 8) {
        const float4 v0 = *(const float4*)&W[(size_t)o * K_IN + c8 * 8];
        const float4 v1 = *(const float4*)&W[(size_t)o * K_IN + c8 * 8 + 4];
        h[0] = __float2half_rn(v0.x); h[1] = __float2half_rn(v0.y);
        h[2] = __float2half_rn(v0.z); h[3] = __float2half_rn(v0.w);
        h[4] = __float2half_rn(v1.x); h[5] = __float2half_rn(v1.y);
        h[6] = __float2half_rn(v1.z); h[7] = __float2half_rn(v1.w);
    } else {
        #pragma unroll
        for (int j = 0; j < 8; j++) {
            const int k = c8 * 8 + j;
            float v;
            if (k < K_IN + R_LORA)       v = loraB[(size_t)o * R_LORA + (k - K_IN)];
            else if (k == K_IN + R_LORA) v = b[o];
            else                         v = 0.0f;
            h[j] = __float2half_rn(v);
        }
    }
    *(uint4*)&g_w[(size_t)o * KP + c8 * 8] = *(const uint4*)h;
}

// ---------------------------------------------------------------------------
// Kernel 4: fp16 GEMM, mma.sync (via wmma) + 4-stage cp.async pipeline.
// CTA 128x128, BK=64, 256 threads (8 warps, 2Mx4N, warp tile 64x32).
// Row pitch 144B -> conflict-free LDSM (r*144 mod 128 = r*16: 8 distinct slots).
// ---------------------------------------------------------------------------
#define BM 128
#define BN 128
#define BK 64
#define STAGES 4
#define PITCH 72                        // halves per row (144 B)
#define TILE_HALFS (128 * PITCH)        // 9216
#define STAGE_HALFS (2 * TILE_HALFS)    // X tile + W tile
#define SMEM_BYTES (STAGES * STAGE_HALFS * 2)   // 147456

__device__ __forceinline__ uint32_t smem_u32(const void* p) {
    return (uint32_t)__cvta_generic_to_shared(p);
}

__global__ __launch_bounds__(256, 1) void gemm_fp16(float* __restrict__ out) {
    extern __shared__ __align__(16) __half smem[];
    const int tid  = threadIdx.x;
    const int warp = tid >> 5;
    const int wm = warp >> 2;       // 0..1
    const int wn = warp & 3;        // 0..3

    // Grouped raster: 16 M-tiles x 32 N-tiles per group (L2 locality)
    const int per = 16 * 32;
    const int pid = blockIdx.x;
    const int gid = pid / per;
    const int rem = pid % per;
    const int mt = gid * 16 + (rem % 16);
    const int nt = rem / 16;
    const size_t rowM = (size_t)mt * BM;
    const size_t rowN = (size_t)nt * BN;

    // ---- chunk loader: 2 tiles x 1024 16B-chunks, 8 cp.async per thread ----
    auto load_chunk = [&](int j, int s) {
        __half* sbase = smem + s * STAGE_HALFS;
        const int k0 = j * BK;
        #pragma unroll
        for (int t = 0; t < 8; t++) {
            const int ch   = t * 256 + tid;
            const int tile = ch >> 10;
            const int idx  = ch & 1023;
            const int r    = idx >> 3;
            const int c    = idx & 7;
            const __half* g = (tile == 0)
                ? g_x + (rowM + r) * KP + k0 + c * 8
                : g_w + (rowN + r) * KP + k0 + c * 8;
            const uint32_t sa = smem_u32(sbase + tile * TILE_HALFS + r * PITCH + c * 8);
            asm volatile("cp.async.cg.shared.global [%0], [%1], 16;"
                         :: "r"(sa), "l"(g) : "memory");
        }
        asm volatile("cp.async.commit_group;" ::: "memory");
    };

    wmma::fragment<wmma::accumulator, 16, 16, 16, float> acc[4][2];
    #pragma unroll
    for (int m = 0; m < 4; m++)
        #pragma unroll
        for (int n = 0; n < 2; n++)
            wmma::fill_fragment(acc[m][n], 0.0f);

    // Prologue: fill STAGES-1 stages
    #pragma unroll
    for (int s = 0; s < STAGES - 1; s++) load_chunk(s, s);

    for (int i = 0; i < NCHUNK; i++) {
        asm volatile("cp.async.wait_group %0;" :: "n"(STAGES - 2) : "memory");
        __syncthreads();   // chunk i visible CTA-wide; stage (i-1)%S now reusable

        const int j = i + STAGES - 1;
        if (j < NCHUNK) load_chunk(j, j % STAGES);

        const __half* sX = smem + (i % STAGES) * STAGE_HALFS;
        const __half* sW = sX + TILE_HALFS;

        #pragma unroll
        for (int ks = 0; ks < 4; ks++) {
            wmma::fragment<wmma::matrix_a, 16, 16, 16, __half, wmma::row_major> a[4];
            wmma::fragment<wmma::matrix_b, 16, 16, 16, __half, wmma::col_major> bf[2];
            #pragma unroll
            for (int m = 0; m < 4; m++)
                wmma::load_matrix_sync(a[m], sX + (wm * 64 + m * 16) * PITCH + ks * 16, PITCH);
            #pragma unroll
            for (int n = 0; n < 2; n++)
                wmma::load_matrix_sync(bf[n], sW + (wn * 32 + n * 16) * PITCH + ks * 16, PITCH);
            #pragma unroll
            for (int m = 0; m < 4; m++)
                #pragma unroll
                for (int n = 0; n < 2; n++)
                    wmma::mma_sync(acc[m][n], a[m], bf[n], acc[m][n]);
        }
    }

    // Epilogue: direct stores (output written exactly once)
    #pragma unroll
    for (int m = 0; m < 4; m++)
        #pragma unroll
        for (int n = 0; n < 2; n++) {
            float* dst = &out[(rowM + wm * 64 + m * 16) * M_OUT +
                              rowN + wn * 32 + n * 16];
            wmma::store_matrix_sync(dst, acc[m][n], M_OUT, wmma::mem_row_major);
        }
}

// ---------------------------------------------------------------------------
// Launch
// ---------------------------------------------------------------------------
extern "C" void kernel_launch(void* const* d_in, const int* in_sizes, int n_in,
                              void* d_out, int out_size) {
    const float* x     = (const float*)d_in[0];
    const float* W     = (const float*)d_in[1];
    const float* b     = (const float*)d_in[2];
    const float* loraA = (const float*)d_in[3];
    const float* loraB = (const float*)d_in[4];
    float* out = (float*)d_out;

    lora_T_kernel<<<N_ROWS / 32, 256>>>(x, loraA);

    const int px = (int)(((size_t)N_ROWS * C8_PER_ROW + 255) / 256);
    pack_x_kernel<<<px, 256>>>(x);
    const int pw = (int)(((size_t)M_OUT * C8_PER_ROW + 255) / 256);
    pack_w_kernel<<<pw, 256>>>(W, b, loraB);

    static bool attr_set = false;
    if (!attr_set) {
        cudaFuncSetAttribute(gemm_fp16, cudaFuncAttributeMaxDynamicSharedMemorySize,
                             SMEM_BYTES);
        attr_set = true;
    }
    const int num_tiles = (N_ROWS / BM) * (M_OUT / BN);   // 2048
    gemm_fp16<<<num_tiles, 256, SMEM_BYTES>>>(out);
}

// round 4
// speedup vs baseline: 5.4652x; 1.1335x over previous
#include <cuda_runtime.h>
#include <cuda_fp16.h>
#include <mma.h>
#include <cstdint>

using namespace nvcuda;

// ---------------------------------------------------------------------------
// Problem constants
// ---------------------------------------------------------------------------
#define N_ROWS 8192
#define K_IN   4096
#define M_OUT  4096
#define R_LORA 16
#define KP     4160          // 4096 + 16 (LoRA) + 1 (bias) + 47 zero pad = 65*64
#define NCHUNK 65            // KP / 64
#define SCALING 2.0f

// Scratch (device globals — no runtime allocation). ~103 MB total.
__device__ __half g_x[(size_t)N_ROWS * KP];
__device__ __half g_w[(size_t)M_OUT * KP];
__device__ float  g_T[(size_t)N_ROWS * R_LORA];

// ---------------------------------------------------------------------------
// Kernel 1: T = SCALING * x @ A^T   (N x 16), fp32 exact.
// ---------------------------------------------------------------------------
__global__ void lora_T_kernel(const float* __restrict__ x,
                              const float* __restrict__ A) {
    __shared__ float sA[16][65];
    __shared__ float sX[32][65];
    const int tid = threadIdx.x;
    const int rowBase = blockIdx.x * 32;
    const int rowLoc = tid & 31;
    const int rGroup = tid >> 5;

    float acc0 = 0.f, acc1 = 0.f;
    for (int k0 = 0; k0 < K_IN; k0 += 64) {
        for (int i = tid; i < 16 * 64; i += 256) {
            int r = i >> 6, kk = i & 63;
            sA[r][kk] = A[r * K_IN + k0 + kk];
        }
        for (int i = tid; i < 32 * 64; i += 256) {
            int rr = i >> 6, kk = i & 63;
            sX[rr][kk] = x[(size_t)(rowBase + rr) * K_IN + k0 + kk];
        }
        __syncthreads();
        #pragma unroll 16
        for (int kk = 0; kk < 64; kk++) {
            float xv = sX[rowLoc][kk];
            acc0 += xv * sA[rGroup * 2 + 0][kk];
            acc1 += xv * sA[rGroup * 2 + 1][kk];
        }
        __syncthreads();
    }
    const int row = rowBase + rowLoc;
    g_T[(size_t)row * R_LORA + rGroup * 2 + 0] = acc0 * SCALING;
    g_T[(size_t)row * R_LORA + rGroup * 2 + 1] = acc1 * SCALING;
}

// ---------------------------------------------------------------------------
// Kernels 2/3: pack augmented operands into fp16. One thread = 8 columns.
// ---------------------------------------------------------------------------
#define C8_PER_ROW (KP / 8)   // 520

__global__ void pack_x_kernel(const float* __restrict__ x) {
    const size_t idx = (size_t)blockIdx.x * blockDim.x + threadIdx.x;
    const int row = (int)(idx / C8_PER_ROW);
    const int c8  = (int)(idx % C8_PER_ROW);
    if (row >= N_ROWS) return;
    __half h[8];
    if (c8 < K_IN / 8) {
        const float4 v0 = *(const float4*)&x[(size_t)row * K_IN + c8 * 8];
        const float4 v1 = *(const float4*)&x[(size_t)row * K_IN + c8 * 8 + 4];
        h[0] = __float2half_rn(v0.x); h[1] = __float2half_rn(v0.y);
        h[2] = __float2half_rn(v0.z); h[3] = __float2half_rn(v0.w);
        h[4] = __float2half_rn(v1.x); h[5] = __float2half_rn(v1.y);
        h[6] = __float2half_rn(v1.z); h[7] = __float2half_rn(v1.w);
    } else {
        #pragma unroll
        for (int j = 0; j < 8; j++) {
            const int k = c8 * 8 + j;
            float v;
            if (k < K_IN + R_LORA)       v = g_T[(size_t)row * R_LORA + (k - K_IN)];
            else if (k == K_IN + R_LORA) v = 1.0f;
            else                         v = 0.0f;
            h[j] = __float2half_rn(v);
        }
    }
    *(uint4*)&g_x[(size_t)row * KP + c8 * 8] = *(const uint4*)h;
}

__global__ void pack_w_kernel(const float* __restrict__ W,
                              const float* __restrict__ b,
                              const float* __restrict__ loraB) {
    const size_t idx = (size_t)blockIdx.x * blockDim.x + threadIdx.x;
    const int o  = (int)(idx / C8_PER_ROW);
    const int c8 = (int)(idx % C8_PER_ROW);
    if (o >= M_OUT) return;
    __half h[8];
    if (c8 < K_IN / 8) {
        const float4 v0 = *(const float4*)&W[(size_t)o * K_IN + c8 * 8];
        const float4 v1 = *(const float4*)&W[(size_t)o * K_IN + c8 * 8 + 4];
        h[0] = __float2half_rn(v0.x); h[1] = __float2half_rn(v0.y);
        h[2] = __float2half_rn(v0.z); h[3] = __float2half_rn(v0.w);
        h[4] = __float2half_rn(v1.x); h[5] = __float2half_rn(v1.y);
        h[6] = __float2half_rn(v1.z); h[7] = __float2half_rn(v1.w);
    } else {
        #pragma unroll
        for (int j = 0; j < 8; j++) {
            const int k = c8 * 8 + j;
            float v;
            if (k < K_IN + R_LORA)       v = loraB[(size_t)o * R_LORA + (k - K_IN)];
            else if (k == K_IN + R_LORA) v = b[o];
            else                         v = 0.0f;
            h[j] = __float2half_rn(v);
        }
    }
    *(uint4*)&g_w[(size_t)o * KP + c8 * 8] = *(const uint4*)h;
}

// ---------------------------------------------------------------------------
// Kernel 4: fp16 GEMM.
// CTA tile 128(M) x 256(N), BK=64, 256 threads, warps 2Mx4N -> 64x64/warp.
// 4-stage cp.async pipeline. Row pitch 144B -> conflict-free LDSM.
// ---------------------------------------------------------------------------
#define BM 128
#define BN 256
#define BK 64
#define STAGES 4
#define PITCH 72                                  // halves per row (144 B)
#define XTILE_HALFS (BM * PITCH)                  // 9216
#define WTILE_HALFS (BN * PITCH)                  // 18432
#define STAGE_HALFS (XTILE_HALFS + WTILE_HALFS)   // 27648
#define SMEM_BYTES (STAGES * STAGE_HALFS * 2)     // 221184

__device__ __forceinline__ uint32_t smem_u32(const void* p) {
    return (uint32_t)__cvta_generic_to_shared(p);
}

__global__ __launch_bounds__(256, 1) void gemm_fp16(float* __restrict__ out) {
    extern __shared__ __align__(16) __half smem[];
    const int tid  = threadIdx.x;
    const int warp = tid >> 5;
    const int wm = warp >> 2;       // 0..1 -> M offset wm*64
    const int wn = warp & 3;        // 0..3 -> N offset wn*64

    // Grouped raster: 8 M-tiles x 16 N-tiles (~1 wave) for L2 locality.
    const int NUM_N = M_OUT / BN;   // 16
    const int GRP = 8;
    const int per = GRP * NUM_N;    // 128
    const int pid = blockIdx.x;
    const int gid = pid / per;
    const int rem = pid % per;
    const int mt = gid * GRP + (rem % GRP);
    const int nt = rem / GRP;
    const size_t rowM = (size_t)mt * BM;
    const size_t rowN = (size_t)nt * BN;

    // ---- chunk loader: X(128x64) + W(256x64) halves, 12 cp.async/thread ----
    auto load_chunk = [&](int j, int s) {
        __half* sbase = smem + s * STAGE_HALFS;
        const int k0 = j * BK;
        #pragma unroll
        for (int t = 0; t < 12; t++) {
            const int ch = t * 256 + tid;          // 0..3071
            const __half* g;
            uint32_t sa;
            if (ch < 1024) {                       // X tile: 128 rows x 8 chunks
                const int r = ch >> 3, c = ch & 7;
                g  = g_x + (rowM + r) * KP + k0 + c * 8;
                sa = smem_u32(sbase + r * PITCH + c * 8);
            } else {                               // W tile: 256 rows x 8 chunks
                const int idx = ch - 1024;
                const int r = idx >> 3, c = idx & 7;
                g  = g_w + (rowN + r) * KP + k0 + c * 8;
                sa = smem_u32(sbase + XTILE_HALFS + r * PITCH + c * 8);
            }
            asm volatile("cp.async.cg.shared.global [%0], [%1], 16;"
                         :: "r"(sa), "l"(g) : "memory");
        }
        asm volatile("cp.async.commit_group;" ::: "memory");
    };

    wmma::fragment<wmma::accumulator, 16, 16, 16, float> acc[4][4];
    #pragma unroll
    for (int m = 0; m < 4; m++)
        #pragma unroll
        for (int n = 0; n < 4; n++)
            wmma::fill_fragment(acc[m][n], 0.0f);

    // Prologue: fill STAGES-1 stages
    #pragma unroll
    for (int s = 0; s < STAGES - 1; s++) load_chunk(s, s);

    for (int i = 0; i < NCHUNK; i++) {
        asm volatile("cp.async.wait_group %0;" :: "n"(STAGES - 2) : "memory");
        __syncthreads();   // chunk i visible; stage (i-1)%S now reusable

        const int j = i + STAGES - 1;
        if (j < NCHUNK) load_chunk(j, j % STAGES);

        const __half* sX = smem + (i % STAGES) * STAGE_HALFS;
        const __half* sW = sX + XTILE_HALFS;

        #pragma unroll
        for (int ks = 0; ks < 4; ks++) {
            wmma::fragment<wmma::matrix_a, 16, 16, 16, __half, wmma::row_major> a[4];
            wmma::fragment<wmma::matrix_b, 16, 16, 16, __half, wmma::col_major> bf[4];
            #pragma unroll
            for (int m = 0; m < 4; m++)
                wmma::load_matrix_sync(a[m], sX + (wm * 64 + m * 16) * PITCH + ks * 16, PITCH);
            #pragma unroll
            for (int n = 0; n < 4; n++)
                wmma::load_matrix_sync(bf[n], sW + (wn * 64 + n * 16) * PITCH + ks * 16, PITCH);
            #pragma unroll
            for (int m = 0; m < 4; m++)
                #pragma unroll
                for (int n = 0; n < 4; n++)
                    wmma::mma_sync(acc[m][n], a[m], bf[n], acc[m][n]);
        }
    }

    // Epilogue: direct stores (each output element written exactly once)
    #pragma unroll
    for (int m = 0; m < 4; m++)
        #pragma unroll
        for (int n = 0; n < 4; n++) {
            float* dst = &out[(rowM + wm * 64 + m * 16) * M_OUT +
                              rowN + wn * 64 + n * 16];
            wmma::store_matrix_sync(dst, acc[m][n], M_OUT, wmma::mem_row_major);
        }
}

// ---------------------------------------------------------------------------
// Launch
// ---------------------------------------------------------------------------
extern "C" void kernel_launch(void* const* d_in, const int* in_sizes, int n_in,
                              void* d_out, int out_size) {
    const float* x     = (const float*)d_in[0];
    const float* W     = (const float*)d_in[1];
    const float* b     = (const float*)d_in[2];
    const float* loraA = (const float*)d_in[3];
    const float* loraB = (const float*)d_in[4];
    float* out = (float*)d_out;

    lora_T_kernel<<<N_ROWS / 32, 256>>>(x, loraA);

    const int px = (int)(((size_t)N_ROWS * C8_PER_ROW + 511) / 512);
    pack_x_kernel<<<px, 512>>>(x);
    const int pw = (int)(((size_t)M_OUT * C8_PER_ROW + 511) / 512);
    pack_w_kernel<<<pw, 512>>>(W, b, loraB);

    static bool attr_set = false;
    if (!attr_set) {
        cudaFuncSetAttribute(gemm_fp16, cudaFuncAttributeMaxDynamicSharedMemorySize,
                             SMEM_BYTES);
        attr_set = true;
    }
    const int num_tiles = (N_ROWS / BM) * (M_OUT / BN);   // 1024
    gemm_fp16<<<num_tiles, 256, SMEM_BYTES>>>(out);
}

// round 5
// speedup vs baseline: 7.0459x; 1.2892x over previous
#include <cuda_runtime.h>
#include <cuda_fp16.h>
#include <mma.h>
#include <cstdint>

using namespace nvcuda;

// ---------------------------------------------------------------------------
// Problem constants
// ---------------------------------------------------------------------------
#define N_ROWS 8192
#define K_IN   4096
#define M_OUT  4096
#define R_LORA 16
#define KP     4160          // 4096 + 1 bias col + 63 zero pad = 65*64
#define NCHUNK 65            // KP / 64
#define SCALING 2.0f

// Scratch (device globals — no runtime allocation). ~103 MB total.
__device__ __half g_x[(size_t)N_ROWS * KP];
__device__ __half g_w[(size_t)M_OUT * KP];

// ---------------------------------------------------------------------------
// Kernel 1: W_eff = W + 2*B@A, packed to fp16.   (folds LoRA into weights)
// Block: 32 o-rows x 512 k-cols. 256 threads: (kq 0..63)*8 k, (og 0..3)*8 o.
// Per thread: 8x8 fp32 acc, 16 r iterations, 64 FMA per a-fragment load.
// ---------------------------------------------------------------------------
#define WEFF_KO 32
#define WEFF_KK 512

__global__ __launch_bounds__(256) void weff_pack_kernel(
        const float* __restrict__ W,
        const float* __restrict__ loraA,
        const float* __restrict__ loraB) {
    __shared__ float sA[16][WEFF_KK + 8];
    __shared__ float sB[WEFF_KO][17];
    const int tid = threadIdx.x;
    const int kbase = blockIdx.x * WEFF_KK;
    const int obase = blockIdx.y * WEFF_KO;

    // Load A chunk [16][512] (coalesced float4)
    for (int i = tid; i < 16 * (WEFF_KK / 4); i += 256) {
        const int r  = i / (WEFF_KK / 4);
        const int c4 = i % (WEFF_KK / 4);
        *(float4*)&sA[r][c4 * 4] =
            *(const float4*)&loraA[(size_t)r * K_IN + kbase + c4 * 4];
    }
    // Load B chunk [32][16], prescaled by SCALING
    for (int i = tid; i < WEFF_KO * 16; i += 256) {
        const int o = i >> 4, r = i & 15;
        sB[o][r] = SCALING * loraB[(size_t)(obase + o) * R_LORA + r];
    }
    __syncthreads();

    const int kq = tid & 63;    // k offset = kq*8
    const int og = tid >> 6;    // o offset = og*8

    float acc[8][8];
    #pragma unroll
    for (int i = 0; i < 8; i++)
        #pragma unroll
        for (int j = 0; j < 8; j++)
            acc[i][j] = 0.f;

    #pragma unroll 4
    for (int r = 0; r < 16; r++) {
        float a[8];
        #pragma unroll
        for (int j = 0; j < 8; j++) a[j] = sA[r][kq * 8 + j];
        #pragma unroll
        for (int oo = 0; oo < 8; oo++) {
            const float bv = sB[og * 8 + oo][r];
            #pragma unroll
            for (int j = 0; j < 8; j++) acc[oo][j] += bv * a[j];
        }
    }

    #pragma unroll
    for (int oo = 0; oo < 8; oo++) {
        const int o = obase + og * 8 + oo;
        const size_t gk = (size_t)o * K_IN + kbase + kq * 8;
        const float4 w0 = *(const float4*)&W[gk];
        const float4 w1 = *(const float4*)&W[gk + 4];
        __half h[8];
        h[0] = __float2half_rn(w0.x + acc[oo][0]);
        h[1] = __float2half_rn(w0.y + acc[oo][1]);
        h[2] = __float2half_rn(w0.z + acc[oo][2]);
        h[3] = __float2half_rn(w0.w + acc[oo][3]);
        h[4] = __float2half_rn(w1.x + acc[oo][4]);
        h[5] = __float2half_rn(w1.y + acc[oo][5]);
        h[6] = __float2half_rn(w1.z + acc[oo][6]);
        h[7] = __float2half_rn(w1.w + acc[oo][7]);
        *(uint4*)&g_w[(size_t)o * KP + kbase + kq * 8] = *(const uint4*)h;
    }
}

// Tail columns [4096, 4160) of g_w: bias at 4096, zeros elsewhere.
__global__ void pack_w_tail(const float* __restrict__ b) {
    const int idx = blockIdx.x * blockDim.x + threadIdx.x;
    const int o = idx >> 6;
    const int c = idx & 63;
    if (o >= M_OUT) return;
    const float v = (c == 0) ? b[o] : 0.f;
    g_w[(size_t)o * KP + K_IN + c] = __float2half_rn(v);
}

// ---------------------------------------------------------------------------
// Kernel 2: pack x into fp16 augmented rows: [x | 1 | 0...].
// ---------------------------------------------------------------------------
#define C8_PER_ROW (KP / 8)   // 520

__global__ void pack_x_kernel(const float* __restrict__ x) {
    const size_t idx = (size_t)blockIdx.x * blockDim.x + threadIdx.x;
    const int row = (int)(idx / C8_PER_ROW);
    const int c8  = (int)(idx % C8_PER_ROW);
    if (row >= N_ROWS) return;
    __half h[8];
    if (c8 < K_IN / 8) {
        const float4 v0 = *(const float4*)&x[(size_t)row * K_IN + c8 * 8];
        const float4 v1 = *(const float4*)&x[(size_t)row * K_IN + c8 * 8 + 4];
        h[0] = __float2half_rn(v0.x); h[1] = __float2half_rn(v0.y);
        h[2] = __float2half_rn(v0.z); h[3] = __float2half_rn(v0.w);
        h[4] = __float2half_rn(v1.x); h[5] = __float2half_rn(v1.y);
        h[6] = __float2half_rn(v1.z); h[7] = __float2half_rn(v1.w);
    } else {
        #pragma unroll
        for (int j = 0; j < 8; j++) {
            const int k = c8 * 8 + j;
            h[j] = __float2half_rn(k == K_IN ? 1.0f : 0.0f);
        }
    }
    *(uint4*)&g_x[(size_t)row * KP + c8 * 8] = *(const uint4*)h;
}

// ---------------------------------------------------------------------------
// Kernel 3: fp16 GEMM (unchanged from R4 — proven 804 us).
// CTA tile 128(M) x 256(N), BK=64, 256 threads, warps 2Mx4N -> 64x64/warp.
// 4-stage cp.async pipeline. Row pitch 144B -> conflict-free LDSM.
// ---------------------------------------------------------------------------
#define BM 128
#define BN 256
#define BK 64
#define STAGES 4
#define PITCH 72                                  // halves per row (144 B)
#define XTILE_HALFS (BM * PITCH)                  // 9216
#define WTILE_HALFS (BN * PITCH)                  // 18432
#define STAGE_HALFS (XTILE_HALFS + WTILE_HALFS)   // 27648
#define SMEM_BYTES (STAGES * STAGE_HALFS * 2)     // 221184

__device__ __forceinline__ uint32_t smem_u32(const void* p) {
    return (uint32_t)__cvta_generic_to_shared(p);
}

__global__ __launch_bounds__(256, 1) void gemm_fp16(float* __restrict__ out) {
    extern __shared__ __align__(16) __half smem[];
    const int tid  = threadIdx.x;
    const int warp = tid >> 5;
    const int wm = warp >> 2;       // 0..1 -> M offset wm*64
    const int wn = warp & 3;        // 0..3 -> N offset wn*64

    // Grouped raster: 8 M-tiles x 16 N-tiles (~1 wave) for L2 locality.
    const int NUM_N = M_OUT / BN;   // 16
    const int GRP = 8;
    const int per = GRP * NUM_N;    // 128
    const int pid = blockIdx.x;
    const int gid = pid / per;
    const int rem = pid % per;
    const int mt = gid * GRP + (rem % GRP);
    const int nt = rem / GRP;
    const size_t rowM = (size_t)mt * BM;
    const size_t rowN = (size_t)nt * BN;

    auto load_chunk = [&](int j, int s) {
        __half* sbase = smem + s * STAGE_HALFS;
        const int k0 = j * BK;
        #pragma unroll
        for (int t = 0; t < 12; t++) {
            const int ch = t * 256 + tid;          // 0..3071
            const __half* g;
            uint32_t sa;
            if (ch < 1024) {                       // X tile: 128 rows x 8 chunks
                const int r = ch >> 3, c = ch & 7;
                g  = g_x + (rowM + r) * KP + k0 + c * 8;
                sa = smem_u32(sbase + r * PITCH + c * 8);
            } else {                               // W tile: 256 rows x 8 chunks
                const int idx = ch - 1024;
                const int r = idx >> 3, c = idx & 7;
                g  = g_w + (rowN + r) * KP + k0 + c * 8;
                sa = smem_u32(sbase + XTILE_HALFS + r * PITCH + c * 8);
            }
            asm volatile("cp.async.cg.shared.global [%0], [%1], 16;"
                         :: "r"(sa), "l"(g) : "memory");
        }
        asm volatile("cp.async.commit_group;" ::: "memory");
    };

    wmma::fragment<wmma::accumulator, 16, 16, 16, float> acc[4][4];
    #pragma unroll
    for (int m = 0; m < 4; m++)
        #pragma unroll
        for (int n = 0; n < 4; n++)
            wmma::fill_fragment(acc[m][n], 0.0f);

    #pragma unroll
    for (int s = 0; s < STAGES - 1; s++) load_chunk(s, s);

    for (int i = 0; i < NCHUNK; i++) {
        asm volatile("cp.async.wait_group %0;" :: "n"(STAGES - 2) : "memory");
        __syncthreads();

        const int j = i + STAGES - 1;
        if (j < NCHUNK) load_chunk(j, j % STAGES);

        const __half* sX = smem + (i % STAGES) * STAGE_HALFS;
        const __half* sW = sX + XTILE_HALFS;

        #pragma unroll
        for (int ks = 0; ks < 4; ks++) {
            wmma::fragment<wmma::matrix_a, 16, 16, 16, __half, wmma::row_major> a[4];
            wmma::fragment<wmma::matrix_b, 16, 16, 16, __half, wmma::col_major> bf[4];
            #pragma unroll
            for (int m = 0; m < 4; m++)
                wmma::load_matrix_sync(a[m], sX + (wm * 64 + m * 16) * PITCH + ks * 16, PITCH);
            #pragma unroll
            for (int n = 0; n < 4; n++)
                wmma::load_matrix_sync(bf[n], sW + (wn * 64 + n * 16) * PITCH + ks * 16, PITCH);
            #pragma unroll
            for (int m = 0; m < 4; m++)
                #pragma unroll
                for (int n = 0; n < 4; n++)
                    wmma::mma_sync(acc[m][n], a[m], bf[n], acc[m][n]);
        }
    }

    #pragma unroll
    for (int m = 0; m < 4; m++)
        #pragma unroll
        for (int n = 0; n < 4; n++) {
            float* dst = &out[(rowM + wm * 64 + m * 16) * M_OUT +
                              rowN + wn * 64 + n * 16];
            wmma::store_matrix_sync(dst, acc[m][n], M_OUT, wmma::mem_row_major);
        }
}

// ---------------------------------------------------------------------------
// Launch
// ---------------------------------------------------------------------------
extern "C" void kernel_launch(void* const* d_in, const int* in_sizes, int n_in,
                              void* d_out, int out_size) {
    const float* x     = (const float*)d_in[0];
    const float* W     = (const float*)d_in[1];
    const float* b     = (const float*)d_in[2];
    const float* loraA = (const float*)d_in[3];
    const float* loraB = (const float*)d_in[4];
    float* out = (float*)d_out;

    // W_eff = W + 2*B@A -> fp16, plus bias/zero tail columns
    dim3 wg(K_IN / WEFF_KK, M_OUT / WEFF_KO);   // (8, 128)
    weff_pack_kernel<<<wg, 256>>>(W, loraA, loraB);
    pack_w_tail<<<(M_OUT * 64) / 256, 256>>>(b);

    // x -> fp16 augmented
    const int px = (int)(((size_t)N_ROWS * C8_PER_ROW + 511) / 512);
    pack_x_kernel<<<px, 512>>>(x);

    static bool attr_set = false;
    if (!attr_set) {
        cudaFuncSetAttribute(gemm_fp16, cudaFuncAttributeMaxDynamicSharedMemorySize,
                             SMEM_BYTES);
        attr_set = true;
    }
    const int num_tiles = (N_ROWS / BM) * (M_OUT / BN);   // 1024
    gemm_fp16<<<num_tiles, 256, SMEM_BYTES>>>(out);
}